// round 16
// baseline (speedup 1.0000x reference)
#include <cuda_runtime.h>
#include <cuda_bf16.h>
#include <cuda_fp16.h>
#include <math.h>

#define BB 4
#define CC 64
#define NN 4096
#define LOG2E 1.4426950408889634f
typedef unsigned int u32;
typedef unsigned long long u64;

__device__ __half g_QTh[(size_t)BB*NN*CC];          // fp16, pre-scaled by log2(e)
__device__ __half g_KTh[(size_t)BB*NN*CC];          // fp16 hi
__device__ __half g_KTl[(size_t)BB*NN*CC];          // fp16 lo (k - hi)
__device__ __nv_bfloat16 g_Vh [(size_t)BB*CC*NN];   // bf16 (range-safe for P*V)

__device__ __forceinline__ u32 smem_u32(const void* p){
    u32 a; asm("{ .reg .u64 t; cvta.to.shared.u64 t, %1; cvt.u32.u64 %0, t; }":"=r"(a):"l"(p)); return a;
}
__device__ __forceinline__ u32 pkbf2(float e0, float e1){     // e0 -> low half (bf16x2)
    u32 r; asm("cvt.rn.bf16x2.f32 %0, %1, %2;" : "=r"(r) : "f"(e1), "f"(e0)); return r;
}
__device__ __forceinline__ u32 pkhf2(float e0, float e1){     // e0 -> low half (f16x2)
    u32 r; asm("cvt.rn.f16x2.f32 %0, %1, %2;" : "=r"(r) : "f"(e1), "f"(e0)); return r;
}
__device__ __forceinline__ float hfround(float a){
    return __half2float(__float2half_rn(a));
}
__device__ __forceinline__ float ex2f(float x){
    float r; asm("ex2.approx.f32 %0,%1;" : "=f"(r) : "f"(x)); return r;
}
// exp2 via FMA polynomial (degree-5), runs on fma/alu pipes instead of MUFU.
__device__ __forceinline__ float ex2poly(float x){
    x = fmaxf(x, -120.f);
    float fi = floorf(x);
    float f = x - fi;
    float p = 0.00133335581f;
    p = fmaf(p, f, 0.00961812911f);
    p = fmaf(p, f, 0.0555041087f);
    p = fmaf(p, f, 0.240226507f);
    p = fmaf(p, f, 0.69314718056f);
    p = fmaf(p, f, 1.0f);
    float sc = __int_as_float(((int)fi + 127) << 23);
    return p * sc;
}
// f32x2 helpers for qkv
__device__ __forceinline__ u64 pk2(float a, float b){
    u64 r; asm("mov.b64 %0,{%1,%2};" : "=l"(r) : "f"(a), "f"(b)); return r;
}
__device__ __forceinline__ void up2(u64 p, float& a, float& b){
    asm("mov.b64 {%0,%1},%2;" : "=f"(a), "=f"(b) : "l"(p));
}
__device__ __forceinline__ void ffma2(u64& d, u64 a, u64 b){
    asm("fma.rn.f32x2 %0,%1,%2,%0;" : "+l"(d) : "l"(a), "l"(b));
}
#define LDSM4(r0,r1,r2,r3,addr) \
    asm volatile("ldmatrix.sync.aligned.m8n8.x4.shared.b16 {%0,%1,%2,%3},[%4];" \
        : "=r"(r0),"=r"(r1),"=r"(r2),"=r"(r3) : "r"(addr))
#define MMAB(d,a0,a1,a2,a3,b0,b1) \
    asm volatile("mma.sync.aligned.m16n8k16.row.col.f32.bf16.bf16.f32 " \
        "{%0,%1,%2,%3},{%4,%5,%6,%7},{%8,%9},{%0,%1,%2,%3};" \
        : "+f"((d)[0]),"+f"((d)[1]),"+f"((d)[2]),"+f"((d)[3]) \
        : "r"(a0),"r"(a1),"r"(a2),"r"(a3),"r"(b0),"r"(b1))
#define MMAH(d,a0,a1,a2,a3,b0,b1) \
    asm volatile("mma.sync.aligned.m16n8k16.row.col.f32.f16.f16.f32 " \
        "{%0,%1,%2,%3},{%4,%5,%6,%7},{%8,%9},{%0,%1,%2,%3};" \
        : "+f"((d)[0]),"+f"((d)[1]),"+f"((d)[2]),"+f"((d)[3]) \
        : "r"(a0),"r"(a1),"r"(a2),"r"(a3),"r"(b0),"r"(b1))
#define CPA(dst,src) \
    asm volatile("cp.async.ca.shared.global [%0],[%1],16;"::"r"(dst),"l"(src))
#define CPA_COMMIT() asm volatile("cp.async.commit_group;":::"memory")
#define CPA_WAIT0()  asm volatile("cp.async.wait_group 0;":::"memory")

// per-buffer smem offsets: K rows 144B stride (hi+lo), V rows 272B stride
#define SK_H 0
#define SK_L 18432
#define SV_H 36864
#define BUFSZ 54272
#define SMEM2 (2*BUFSZ)   // 108,544 B

// ------------------- Kernel 1: QKV, f32x2-packed inner loop -------------------
__global__ void __launch_bounds__(256) qkv_kernel(
    const float* __restrict__ x,
    const float* __restrict__ Wq, const float* __restrict__ bq,
    const float* __restrict__ Wk, const float* __restrict__ bk,
    const float* __restrict__ Wv, const float* __restrict__ bv)
{
    extern __shared__ float sm1[];
    float* xs  = sm1;            // [64][64]
    float* wtq = sm1 + 4096;     // [64][68]
    float* wtk = wtq + 64*68;
    float* wtv = wtk + 64*68;
    const int t = threadIdx.x, b = blockIdx.y, nbase = blockIdx.x*64;

    for (int idx = t; idx < 64*64; idx += 256) {
        int o = idx>>6, c = idx&63;
        wtq[c*68+o]=Wq[idx]; wtk[c*68+o]=Wk[idx]; wtv[c*68+o]=Wv[idx];
    }
    const float* xb = x + (size_t)b*CC*NN + nbase;
    for (int i4 = t; i4 < 1024; i4 += 256) {
        int c = i4>>4, n4 = (i4&15)<<2;
        *(float4*)&xs[c*64+n4] = *(const float4*)&xb[(size_t)c*NN+n4];
    }
    __syncthreads();
    const int ty = t>>4, tx = t&15, o0 = ty*4, n0 = tx*4;

    // accumulators packed along r-pairs: acc[rp][s] = (val_r0, val_r1)
    u64 qa[2][4], ka[2][4], va[2][4];
    #pragma unroll
    for (int rp = 0; rp < 2; rp++) {
        u64 bq2 = pk2(bq[o0+2*rp], bq[o0+2*rp+1]);
        u64 bk2 = pk2(bk[o0+2*rp], bk[o0+2*rp+1]);
        u64 bv2 = pk2(bv[o0+2*rp], bv[o0+2*rp+1]);
        #pragma unroll
        for (int s = 0; s < 4; s++){ qa[rp][s]=bq2; ka[rp][s]=bk2; va[rp][s]=bv2; }
    }
    #pragma unroll 4
    for (int c = 0; c < 64; c++) {
        float wq[4], wk[4], wv[4], xr[4];
        *(float4*)&wq[0]=*(float4*)&wtq[c*68+o0];
        *(float4*)&wk[0]=*(float4*)&wtk[c*68+o0];
        *(float4*)&wv[0]=*(float4*)&wtv[c*68+o0];
        *(float4*)&xr[0]=*(float4*)&xs[c*64+n0];
        u64 wq01 = pk2(wq[0],wq[1]), wq23 = pk2(wq[2],wq[3]);
        u64 wk01 = pk2(wk[0],wk[1]), wk23 = pk2(wk[2],wk[3]);
        u64 wv01 = pk2(wv[0],wv[1]), wv23 = pk2(wv[2],wv[3]);
        #pragma unroll
        for (int s = 0; s < 4; s++) {
            u64 xd = pk2(xr[s], xr[s]);
            ffma2(qa[0][s], wq01, xd); ffma2(qa[1][s], wq23, xd);
            ffma2(ka[0][s], wk01, xd); ffma2(ka[1][s], wk23, xd);
            ffma2(va[0][s], wv01, xd); ffma2(va[1][s], wv23, xd);
        }
    }
    // unpack
    float aq[4][4], ak[4][4], av[4][4];
    #pragma unroll
    for (int rp = 0; rp < 2; rp++)
        #pragma unroll
        for (int s = 0; s < 4; s++) {
            up2(qa[rp][s], aq[2*rp][s], aq[2*rp+1][s]);
            up2(ka[rp][s], ak[2*rp][s], ak[2*rp+1][s]);
            up2(va[rp][s], av[2*rp][s], av[2*rp+1][s]);
        }

    // V (bf16): natural [c][n]
    #pragma unroll
    for (int r = 0; r < 4; r++) {
        size_t off = (size_t)b*CC*NN + (size_t)(o0+r)*NN + nbase + n0;
        *(u32*)(g_Vh+off)   = pkbf2(av[r][0], av[r][1]);
        *(u32*)(g_Vh+off+2) = pkbf2(av[r][2], av[r][3]);
    }
    // Q transposed [n][c], fp16, pre-scaled by log2(e)
    #pragma unroll
    for (int s = 0; s < 4; s++) {
        size_t gb = ((size_t)b*NN + nbase + n0 + s)*CC + o0;
        uint2 hv;
        hv.x = pkhf2(aq[0][s]*LOG2E, aq[1][s]*LOG2E);
        hv.y = pkhf2(aq[2][s]*LOG2E, aq[3][s]*LOG2E);
        *(uint2*)(g_QTh+gb) = hv;
    }
    // K transposed [n][c], fp16 hi/lo
    #pragma unroll
    for (int s = 0; s < 4; s++) {
        size_t gb = ((size_t)b*NN + nbase + n0 + s)*CC + o0;
        float k0 = ak[0][s], k1 = ak[1][s], k2 = ak[2][s], k3 = ak[3][s];
        float h0 = hfround(k0), h1 = hfround(k1), h2 = hfround(k2), h3 = hfround(k3);
        uint2 hv; hv.x = pkhf2(h0, h1); hv.y = pkhf2(h2, h3);
        *(uint2*)(g_KTh+gb) = hv;
        uint2 lv; lv.x = pkhf2(k0-h0, k1-h1); lv.y = pkhf2(k2-h2, k3-h3);
        *(uint2*)(g_KTl+gb) = lv;
    }
}

// prefetch one K(hi+lo fp16)/V(bf16) tile into smem buffer via cp.async
__device__ __forceinline__ void prefetch_tile(
    char* smbuf,
    const __half* kh, const __half* kl,
    const __nv_bfloat16* vh, int jt, int t)
{
    const u32 sbuf = smem_u32(smbuf);
    #pragma unroll
    for (int k = 0; k < 4; k++) {
        int idx = t + k*256, row = idx>>3, ch = idx&7;
        CPA(sbuf + SK_H + row*144 + ch*16, (const char*)(kh + (size_t)(jt+row)*CC) + ch*16);
        CPA(sbuf + SK_L + row*144 + ch*16, (const char*)(kl + (size_t)(jt+row)*CC) + ch*16);
    }
    #pragma unroll
    for (int k = 0; k < 4; k++) {
        int idx = t + k*256, row = idx>>4, ch = idx&15;
        CPA(sbuf + SV_H + row*272 + ch*16, (const char*)(vh + (size_t)row*NN + jt) + ch*16);
    }
}

// ------------------- Kernel 2: HMMA flash attention, MUFU/FMA-split exp -------------------
__global__ void __launch_bounds__(256) attn_kernel(
    const float* __restrict__ x, const float* __restrict__ gamma,
    float* __restrict__ out)
{
    extern __shared__ __align__(16) char sm2[];
    const int t = threadIdx.x, wid = t>>5, lane = t&31;
    const int rg = wid & 3, jh = wid >> 2;
    const int i0 = rg*32;
    const int jcol0 = jh*64;
    const int b = blockIdx.y, ibase = blockIdx.x*128;

    const __half* qh = g_QTh + (size_t)b*NN*CC;
    const __half* kh = g_KTh + (size_t)b*NN*CC;
    const __half* kl = g_KTl + (size_t)b*NN*CC;
    const __nv_bfloat16* vh = g_Vh + (size_t)b*CC*NN;

    // prefetch tile 0 -> buf0; stage Q (hi only) -> buf1 K area
    prefetch_tile(sm2, kh, kl, vh, 0, t);
    {
        const u32 sq = smem_u32(sm2 + BUFSZ);
        #pragma unroll
        for (int k = 0; k < 4; k++) {
            int idx = t + k*256, row = idx>>3, ch = idx&7;
            CPA(sq + SK_H + row*144 + ch*16, (const char*)(qh + (size_t)(ibase+row)*CC) + ch*16);
        }
    }
    CPA_COMMIT();
    CPA_WAIT0();
    __syncthreads();

    // Q A-frags (fp16) for the warp's two m16 blocks
    u32 qf[2][4][4];
    #pragma unroll
    for (int mb = 0; mb < 2; mb++) {
        u32 abase = smem_u32(sm2 + BUFSZ) + (u32)((i0 + mb*16 + (lane&15))*144 + ((lane>>4)*16));
        #pragma unroll
        for (int ks = 0; ks < 4; ks++)
            LDSM4(qf[mb][ks][0],qf[mb][ks][1],qf[mb][ks][2],qf[mb][ks][3], abase + ks*32);
    }
    __syncthreads();   // Q staging (buf1) free for tile-1 prefetch

    float O[2][8][4];
    #pragma unroll
    for (int mb = 0; mb < 2; mb++)
        #pragma unroll
        for (int nb = 0; nb < 8; nb++)
            #pragma unroll
            for (int k = 0; k < 4; k++) O[mb][nb][k] = 0.f;
    float srow[2][2] = {{0.f,0.f},{0.f,0.f}};

    for (int tile = 0; tile < 32; tile++) {
        char* cur = sm2 + (tile & 1)*BUFSZ;
        char* nxt = sm2 + ((tile & 1)^1)*BUFSZ;
        if (tile > 0) { CPA_WAIT0(); __syncthreads(); }
        if (tile < 31) { prefetch_tile(nxt, kh, kl, vh, (tile+1)<<7, t); CPA_COMMIT(); }

        const u32 sb = smem_u32(cur);

        #pragma unroll
        for (int hh = 0; hh < 2; hh++) {
            const int h = hh ^ jh;        // stagger halves across SMSP warp pairs

            // ---- GEMM1 half: S[32 x 32] = Qh*Kh + Qh*Kl, K-frags double-buffered ----
            float S[2][4][4];
            u32 kf[2][16];
            {
                u32 base = sb + SK_H + (u32)(((jcol0 + (h*4)*8 + (lane&7))*144) + ((lane>>3)*16));
                LDSM4(kf[0][0],kf[0][1],kf[0][2],kf[0][3], base);
                LDSM4(kf[0][4],kf[0][5],kf[0][6],kf[0][7], base + 64);
                LDSM4(kf[0][8],kf[0][9],kf[0][10],kf[0][11], base + 18432);
                LDSM4(kf[0][12],kf[0][13],kf[0][14],kf[0][15], base + 18432 + 64);
            }
            #pragma unroll
            for (int nbl = 0; nbl < 4; nbl++) {
                const int cb = nbl & 1;
                if (nbl < 3) {
                    const int nxb = cb ^ 1;
                    u32 base = sb + SK_H + (u32)(((jcol0 + (h*4+nbl+1)*8 + (lane&7))*144) + ((lane>>3)*16));
                    LDSM4(kf[nxb][0],kf[nxb][1],kf[nxb][2],kf[nxb][3], base);
                    LDSM4(kf[nxb][4],kf[nxb][5],kf[nxb][6],kf[nxb][7], base + 64);
                    LDSM4(kf[nxb][8],kf[nxb][9],kf[nxb][10],kf[nxb][11], base + 18432);
                    LDSM4(kf[nxb][12],kf[nxb][13],kf[nxb][14],kf[nxb][15], base + 18432 + 64);
                }
                const u32* K = kf[cb];
                #pragma unroll
                for (int mb = 0; mb < 2; mb++) {
                    float* D = S[mb][nbl];
                    D[0]=D[1]=D[2]=D[3]=0.f;
                    MMAH(D, qf[mb][0][0],qf[mb][0][1],qf[mb][0][2],qf[mb][0][3], K[0],K[1]);
                    MMAH(D, qf[mb][1][0],qf[mb][1][1],qf[mb][1][2],qf[mb][1][3], K[2],K[3]);
                    MMAH(D, qf[mb][2][0],qf[mb][2][1],qf[mb][2][2],qf[mb][2][3], K[4],K[5]);
                    MMAH(D, qf[mb][3][0],qf[mb][3][1],qf[mb][3][2],qf[mb][3][3], K[6],K[7]);
                    MMAH(D, qf[mb][0][0],qf[mb][0][1],qf[mb][0][2],qf[mb][0][3], K[8],K[9]);
                    MMAH(D, qf[mb][1][0],qf[mb][1][1],qf[mb][1][2],qf[mb][1][3], K[10],K[11]);
                    MMAH(D, qf[mb][2][0],qf[mb][2][1],qf[mb][2][2],qf[mb][2][3], K[12],K[13]);
                    MMAH(D, qf[mb][3][0],qf[mb][3][1],qf[mb][3][2],qf[mb][3][3], K[14],K[15]);
                }
            }

            // ---- exp2: half MUFU, half FMA-poly (pipe balance) + pack P (bf16) ----
            u32 ahh[2][2][4];
            #pragma unroll
            for (int mb = 0; mb < 2; mb++) {
                #pragma unroll
                for (int ksl = 0; ksl < 2; ksl++) {
                    const float* SA = S[mb][2*ksl];
                    const float* SB = S[mb][2*ksl+1];
                    float eA0 = ex2f(SA[0]),    eA1 = ex2f(SA[1]);
                    float eA2 = ex2poly(SA[2]), eA3 = ex2poly(SA[3]);
                    float eB0 = ex2f(SB[0]),    eB1 = ex2f(SB[1]);
                    float eB2 = ex2poly(SB[2]), eB3 = ex2poly(SB[3]);
                    srow[mb][0] += (eA0 + eA1) + (eB0 + eB1);
                    srow[mb][1] += (eA2 + eA3) + (eB2 + eB3);
                    ahh[mb][ksl][0] = pkbf2(eA0, eA1);
                    ahh[mb][ksl][1] = pkbf2(eA2, eA3);
                    ahh[mb][ksl][2] = pkbf2(eB0, eB1);
                    ahh[mb][ksl][3] = pkbf2(eB2, eB3);
                }
            }

            // ---- GEMM2 half: O += Ph*Vh (bf16), V-frags double-buffered ----
            u32 vf[2][4];
            {
                u32 base = sb + SV_H + (u32)(((lane&7))*272 + jcol0*2 + ((lane>>3)*16)) + h*64;
                LDSM4(vf[0][0],vf[0][1],vf[0][2],vf[0][3], base);
            }
            #pragma unroll
            for (int nbO = 0; nbO < 8; nbO++) {
                const int cb = nbO & 1;
                if (nbO < 7) {
                    const int nxb = cb ^ 1;
                    u32 base = sb + SV_H + (u32)(((nbO+1)*8 + (lane&7))*272 + jcol0*2 + ((lane>>3)*16)) + h*64;
                    LDSM4(vf[nxb][0],vf[nxb][1],vf[nxb][2],vf[nxb][3], base);
                }
                const u32* V = vf[cb];
                #pragma unroll
                for (int mb = 0; mb < 2; mb++) {
                    float* D = O[mb][nbO];
                    MMAB(D, ahh[mb][0][0],ahh[mb][0][1],ahh[mb][0][2],ahh[mb][0][3], V[0],V[1]);
                    MMAB(D, ahh[mb][1][0],ahh[mb][1][1],ahh[mb][1][2],ahh[mb][1][3], V[2],V[3]);
                }
            }
        }
    }

    // ---- epilogue: combine j-halves ----
    #pragma unroll
    for (int mb = 0; mb < 2; mb++)
        #pragma unroll
        for (int rr = 0; rr < 2; rr++) {
            float v = srow[mb][rr];
            v += __shfl_xor_sync(0xffffffffu, v, 1);
            v += __shfl_xor_sync(0xffffffffu, v, 2);
            srow[mb][rr] = v;
        }

    float* Stg = (float*)sm2;                 // [128 threads][68] padded
    float* Ls  = (float*)(sm2 + 36864);       // [128 rows][2]
    if ((lane & 3) == 0) {
        #pragma unroll
        for (int mb = 0; mb < 2; mb++) {
            int row = i0 + mb*16 + (lane>>2);
            Ls[row*2 + jh]     = srow[mb][0];
            Ls[(row+8)*2 + jh] = srow[mb][1];
        }
    }
    if (jh == 1) {
        float* dst = Stg + (rg*32 + lane)*68;
        #pragma unroll
        for (int mb = 0; mb < 2; mb++)
            #pragma unroll
            for (int nb = 0; nb < 8; nb++)
                *(float4*)&dst[(mb*8+nb)*4] = *(float4*)O[mb][nb];
    }
    __syncthreads();

    if (jh == 0) {
        const float g = gamma[0];
        const float* src = Stg + (rg*32 + lane)*68;
        float rs[2][2];
        #pragma unroll
        for (int mb = 0; mb < 2; mb++) {
            int row = i0 + mb*16 + (lane>>2);
            rs[mb][0] = 1.0f / (Ls[row*2]     + Ls[row*2 + 1]);
            rs[mb][1] = 1.0f / (Ls[(row+8)*2] + Ls[(row+8)*2 + 1]);
        }
        #pragma unroll
        for (int mb = 0; mb < 2; mb++) {
            #pragma unroll
            for (int nb = 0; nb < 8; nb++) {
                float4 p = *(const float4*)&src[(mb*8+nb)*4];
                float o0 = O[mb][nb][0] + p.x;
                float o1 = O[mb][nb][1] + p.y;
                float o2 = O[mb][nb][2] + p.z;
                float o3 = O[mb][nb][3] + p.w;
                int irow = ibase + i0 + mb*16 + (lane>>2);
                int c = nb*8 + (lane&3)*2;
                size_t off = (size_t)b*CC*NN + (size_t)c*NN + irow;
                out[off]      = g*(o0*rs[mb][0]) + x[off];
                out[off+NN]   = g*(o1*rs[mb][0]) + x[off+NN];
                out[off+8]    = g*(o2*rs[mb][1]) + x[off+8];
                out[off+NN+8] = g*(o3*rs[mb][1]) + x[off+NN+8];
            }
        }
    }
}

// ---------------------------------------------------------------------------
extern "C" void kernel_launch(void* const* d_in, const int* in_sizes, int n_in,
                              void* d_out, int out_size)
{
    const float* x     = (const float*)d_in[0];
    const float* Wq    = (const float*)d_in[1];
    const float* bq    = (const float*)d_in[2];
    const float* Wk    = (const float*)d_in[3];
    const float* bk    = (const float*)d_in[4];
    const float* Wv    = (const float*)d_in[5];
    const float* bv    = (const float*)d_in[6];
    const float* gamma = (const float*)d_in[7];
    float* out = (float*)d_out;

    const int smem1 = (4096 + 3*64*68) * sizeof(float);  // 68,608 B -> 2 CTAs/SM
    const int smem2 = SMEM2;                             // 108,544 B

    cudaFuncSetAttribute(qkv_kernel,  cudaFuncAttributeMaxDynamicSharedMemorySize, smem1);
    cudaFuncSetAttribute(attn_kernel, cudaFuncAttributeMaxDynamicSharedMemorySize, smem2);

    qkv_kernel<<<dim3(64, 4), 256, smem1>>>(x, Wq, bq, Wk, bk, Wv, bv);
    attn_kernel<<<dim3(32, 4), 256, smem2>>>(x, gamma, out);
}

// round 17
// speedup vs baseline: 1.2206x; 1.2206x over previous
#include <cuda_runtime.h>
#include <cuda_bf16.h>
#include <cuda_fp16.h>
#include <math.h>

#define BB 4
#define CC 64
#define NN 4096
#define LOG2E 1.4426950408889634f
typedef unsigned int u32;
typedef unsigned long long u64;

__device__ __half g_QTh[(size_t)BB*NN*CC];          // fp16, pre-scaled by log2(e)
__device__ __half g_KTh[(size_t)BB*NN*CC];          // fp16 hi
__device__ __half g_KTl[(size_t)BB*NN*CC];          // fp16 lo (k - hi)
__device__ __nv_bfloat16 g_Vh [(size_t)BB*CC*NN];   // bf16 (range-safe for P*V)

__device__ __forceinline__ u32 smem_u32(const void* p){
    u32 a; asm("{ .reg .u64 t; cvta.to.shared.u64 t, %1; cvt.u32.u64 %0, t; }":"=r"(a):"l"(p)); return a;
}
__device__ __forceinline__ u32 pkbf2(float e0, float e1){     // e0 -> low half (bf16x2)
    u32 r; asm("cvt.rn.bf16x2.f32 %0, %1, %2;" : "=r"(r) : "f"(e1), "f"(e0)); return r;
}
__device__ __forceinline__ u32 pkhf2(float e0, float e1){     // e0 -> low half (f16x2)
    u32 r; asm("cvt.rn.f16x2.f32 %0, %1, %2;" : "=r"(r) : "f"(e1), "f"(e0)); return r;
}
__device__ __forceinline__ float hfround(float a){
    return __half2float(__float2half_rn(a));
}
__device__ __forceinline__ float ex2f(float x){
    float r; asm("ex2.approx.f32 %0,%1;" : "=f"(r) : "f"(x)); return r;
}
// f32x2 helpers for qkv
__device__ __forceinline__ u64 pk2(float a, float b){
    u64 r; asm("mov.b64 %0,{%1,%2};" : "=l"(r) : "f"(a), "f"(b)); return r;
}
__device__ __forceinline__ void up2(u64 p, float& a, float& b){
    asm("mov.b64 {%0,%1},%2;" : "=f"(a), "=f"(b) : "l"(p));
}
__device__ __forceinline__ void ffma2(u64& d, u64 a, u64 b){
    asm("fma.rn.f32x2 %0,%1,%2,%0;" : "+l"(d) : "l"(a), "l"(b));
}
#define LDSM4(r0,r1,r2,r3,addr) \
    asm volatile("ldmatrix.sync.aligned.m8n8.x4.shared.b16 {%0,%1,%2,%3},[%4];" \
        : "=r"(r0),"=r"(r1),"=r"(r2),"=r"(r3) : "r"(addr))
#define MMAB(d,a0,a1,a2,a3,b0,b1) \
    asm volatile("mma.sync.aligned.m16n8k16.row.col.f32.bf16.bf16.f32 " \
        "{%0,%1,%2,%3},{%4,%5,%6,%7},{%8,%9},{%0,%1,%2,%3};" \
        : "+f"((d)[0]),"+f"((d)[1]),"+f"((d)[2]),"+f"((d)[3]) \
        : "r"(a0),"r"(a1),"r"(a2),"r"(a3),"r"(b0),"r"(b1))
#define MMAH(d,a0,a1,a2,a3,b0,b1) \
    asm volatile("mma.sync.aligned.m16n8k16.row.col.f32.f16.f16.f32 " \
        "{%0,%1,%2,%3},{%4,%5,%6,%7},{%8,%9},{%0,%1,%2,%3};" \
        : "+f"((d)[0]),"+f"((d)[1]),"+f"((d)[2]),"+f"((d)[3]) \
        : "r"(a0),"r"(a1),"r"(a2),"r"(a3),"r"(b0),"r"(b1))
#define CPA(dst,src) \
    asm volatile("cp.async.ca.shared.global [%0],[%1],16;"::"r"(dst),"l"(src))
#define CPA_COMMIT() asm volatile("cp.async.commit_group;":::"memory")
#define CPA_WAIT0()  asm volatile("cp.async.wait_group 0;":::"memory")

// per-buffer smem offsets: K rows 144B stride (hi+lo), V rows 272B stride
#define SK_H 0
#define SK_L 18432
#define SV_H 36864
#define BUFSZ 54272
#define SMEM2 (2*BUFSZ)   // 108,544 B

// ------------------- Kernel 1: QKV, f32x2-packed inner loop -------------------
__global__ void __launch_bounds__(256) qkv_kernel(
    const float* __restrict__ x,
    const float* __restrict__ Wq, const float* __restrict__ bq,
    const float* __restrict__ Wk, const float* __restrict__ bk,
    const float* __restrict__ Wv, const float* __restrict__ bv)
{
    extern __shared__ float sm1[];
    float* xs  = sm1;            // [64][64]
    float* wtq = sm1 + 4096;     // [64][68]
    float* wtk = wtq + 64*68;
    float* wtv = wtk + 64*68;
    const int t = threadIdx.x, b = blockIdx.y, nbase = blockIdx.x*64;

    for (int idx = t; idx < 64*64; idx += 256) {
        int o = idx>>6, c = idx&63;
        wtq[c*68+o]=Wq[idx]; wtk[c*68+o]=Wk[idx]; wtv[c*68+o]=Wv[idx];
    }
    const float* xb = x + (size_t)b*CC*NN + nbase;
    for (int i4 = t; i4 < 1024; i4 += 256) {
        int c = i4>>4, n4 = (i4&15)<<2;
        *(float4*)&xs[c*64+n4] = *(const float4*)&xb[(size_t)c*NN+n4];
    }
    __syncthreads();
    const int ty = t>>4, tx = t&15, o0 = ty*4, n0 = tx*4;

    u64 qa[2][4], ka[2][4], va[2][4];
    #pragma unroll
    for (int rp = 0; rp < 2; rp++) {
        u64 bq2 = pk2(bq[o0+2*rp], bq[o0+2*rp+1]);
        u64 bk2 = pk2(bk[o0+2*rp], bk[o0+2*rp+1]);
        u64 bv2 = pk2(bv[o0+2*rp], bv[o0+2*rp+1]);
        #pragma unroll
        for (int s = 0; s < 4; s++){ qa[rp][s]=bq2; ka[rp][s]=bk2; va[rp][s]=bv2; }
    }
    #pragma unroll 4
    for (int c = 0; c < 64; c++) {
        float wq[4], wk[4], wv[4], xr[4];
        *(float4*)&wq[0]=*(float4*)&wtq[c*68+o0];
        *(float4*)&wk[0]=*(float4*)&wtk[c*68+o0];
        *(float4*)&wv[0]=*(float4*)&wtv[c*68+o0];
        *(float4*)&xr[0]=*(float4*)&xs[c*64+n0];
        u64 wq01 = pk2(wq[0],wq[1]), wq23 = pk2(wq[2],wq[3]);
        u64 wk01 = pk2(wk[0],wk[1]), wk23 = pk2(wk[2],wk[3]);
        u64 wv01 = pk2(wv[0],wv[1]), wv23 = pk2(wv[2],wv[3]);
        #pragma unroll
        for (int s = 0; s < 4; s++) {
            u64 xd = pk2(xr[s], xr[s]);
            ffma2(qa[0][s], wq01, xd); ffma2(qa[1][s], wq23, xd);
            ffma2(ka[0][s], wk01, xd); ffma2(ka[1][s], wk23, xd);
            ffma2(va[0][s], wv01, xd); ffma2(va[1][s], wv23, xd);
        }
    }
    float aq[4][4], ak[4][4], av[4][4];
    #pragma unroll
    for (int rp = 0; rp < 2; rp++)
        #pragma unroll
        for (int s = 0; s < 4; s++) {
            up2(qa[rp][s], aq[2*rp][s], aq[2*rp+1][s]);
            up2(ka[rp][s], ak[2*rp][s], ak[2*rp+1][s]);
            up2(va[rp][s], av[2*rp][s], av[2*rp+1][s]);
        }

    // V (bf16): natural [c][n]
    #pragma unroll
    for (int r = 0; r < 4; r++) {
        size_t off = (size_t)b*CC*NN + (size_t)(o0+r)*NN + nbase + n0;
        *(u32*)(g_Vh+off)   = pkbf2(av[r][0], av[r][1]);
        *(u32*)(g_Vh+off+2) = pkbf2(av[r][2], av[r][3]);
    }
    // Q transposed [n][c], fp16, pre-scaled by log2(e)
    #pragma unroll
    for (int s = 0; s < 4; s++) {
        size_t gb = ((size_t)b*NN + nbase + n0 + s)*CC + o0;
        uint2 hv;
        hv.x = pkhf2(aq[0][s]*LOG2E, aq[1][s]*LOG2E);
        hv.y = pkhf2(aq[2][s]*LOG2E, aq[3][s]*LOG2E);
        *(uint2*)(g_QTh+gb) = hv;
    }
    // K transposed [n][c], fp16 hi/lo
    #pragma unroll
    for (int s = 0; s < 4; s++) {
        size_t gb = ((size_t)b*NN + nbase + n0 + s)*CC + o0;
        float k0 = ak[0][s], k1 = ak[1][s], k2 = ak[2][s], k3 = ak[3][s];
        float h0 = hfround(k0), h1 = hfround(k1), h2 = hfround(k2), h3 = hfround(k3);
        uint2 hv; hv.x = pkhf2(h0, h1); hv.y = pkhf2(h2, h3);
        *(uint2*)(g_KTh+gb) = hv;
        uint2 lv; lv.x = pkhf2(k0-h0, k1-h1); lv.y = pkhf2(k2-h2, k3-h3);
        *(uint2*)(g_KTl+gb) = lv;
    }
}

// prefetch one K(hi+lo fp16)/V(bf16) tile into smem buffer via cp.async
__device__ __forceinline__ void prefetch_tile(
    char* smbuf,
    const __half* kh, const __half* kl,
    const __nv_bfloat16* vh, int jt, int t)
{
    const u32 sbuf = smem_u32(smbuf);
    #pragma unroll
    for (int k = 0; k < 4; k++) {
        int idx = t + k*256, row = idx>>3, ch = idx&7;
        CPA(sbuf + SK_H + row*144 + ch*16, (const char*)(kh + (size_t)(jt+row)*CC) + ch*16);
        CPA(sbuf + SK_L + row*144 + ch*16, (const char*)(kl + (size_t)(jt+row)*CC) + ch*16);
    }
    #pragma unroll
    for (int k = 0; k < 4; k++) {
        int idx = t + k*256, row = idx>>4, ch = idx&15;
        CPA(sbuf + SV_H + row*272 + ch*16, (const char*)(vh + (size_t)row*NN + jt) + ch*16);
    }
}

// ------------------- Kernel 2: HMMA flash attention, deferred-GEMM2 overlap -------------------
// Per tile: GEMM1(A) -> exp(A) -> GEMM1(B) -> exp(B) -> GEMM2(A) -> GEMM2(B).
// GEMM1(B) and GEMM2(A) are independent of the adjacent MUFU bursts, giving
// ptxas HMMA/LDSM work to interleave into each exp burst's stall shadow.
__global__ void __launch_bounds__(256) attn_kernel(
    const float* __restrict__ x, const float* __restrict__ gamma,
    float* __restrict__ out)
{
    extern __shared__ __align__(16) char sm2[];
    const int t = threadIdx.x, wid = t>>5, lane = t&31;
    const int rg = wid & 3, jh = wid >> 2;
    const int i0 = rg*32;
    const int jcol0 = jh*64;
    const int b = blockIdx.y, ibase = blockIdx.x*128;

    const __half* qh = g_QTh + (size_t)b*NN*CC;
    const __half* kh = g_KTh + (size_t)b*NN*CC;
    const __half* kl = g_KTl + (size_t)b*NN*CC;
    const __nv_bfloat16* vh = g_Vh + (size_t)b*CC*NN;

    // prefetch tile 0 -> buf0; stage Q (fp16) -> buf1 K area
    prefetch_tile(sm2, kh, kl, vh, 0, t);
    {
        const u32 sq = smem_u32(sm2 + BUFSZ);
        #pragma unroll
        for (int k = 0; k < 4; k++) {
            int idx = t + k*256, row = idx>>3, ch = idx&7;
            CPA(sq + SK_H + row*144 + ch*16, (const char*)(qh + (size_t)(ibase+row)*CC) + ch*16);
        }
    }
    CPA_COMMIT();
    CPA_WAIT0();
    __syncthreads();

    // Q A-frags (fp16) for the warp's two m16 blocks
    u32 qf[2][4][4];
    #pragma unroll
    for (int mb = 0; mb < 2; mb++) {
        u32 abase = smem_u32(sm2 + BUFSZ) + (u32)((i0 + mb*16 + (lane&15))*144 + ((lane>>4)*16));
        #pragma unroll
        for (int ks = 0; ks < 4; ks++)
            LDSM4(qf[mb][ks][0],qf[mb][ks][1],qf[mb][ks][2],qf[mb][ks][3], abase + ks*32);
    }
    __syncthreads();   // Q staging (buf1) free for tile-1 prefetch

    float O[2][8][4];
    #pragma unroll
    for (int mb = 0; mb < 2; mb++)
        #pragma unroll
        for (int nb = 0; nb < 8; nb++)
            #pragma unroll
            for (int k = 0; k < 4; k++) O[mb][nb][k] = 0.f;
    float srow[2][2] = {{0.f,0.f},{0.f,0.f}};

    for (int tile = 0; tile < 32; tile++) {
        char* cur = sm2 + (tile & 1)*BUFSZ;
        char* nxt = sm2 + ((tile & 1)^1)*BUFSZ;
        if (tile > 0) { CPA_WAIT0(); __syncthreads(); }
        if (tile < 31) { prefetch_tile(nxt, kh, kl, vh, (tile+1)<<7, t); CPA_COMMIT(); }

        const u32 sb = smem_u32(cur);

        u32 ahh2[2][2][2][4];     // [phase][mb][ksl][4]

        // ---- Phase loop: GEMM1 + exp for both halves (GEMM2 deferred) ----
        #pragma unroll
        for (int ph = 0; ph < 2; ph++) {
            const int h = ph ^ jh;

            float S[2][4][4];
            #pragma unroll
            for (int nbl = 0; nbl < 4; nbl++) {
                u32 base = sb + SK_H + (u32)(((jcol0 + (h*4+nbl)*8 + (lane&7))*144) + ((lane>>3)*16));
                u32 k0,k1,k2,k3,k4,k5,k6,k7, l0,l1,l2,l3,l4,l5,l6,l7;
                LDSM4(k0,k1,k2,k3, base);
                LDSM4(k4,k5,k6,k7, base + 64);
                LDSM4(l0,l1,l2,l3, base + 18432);
                LDSM4(l4,l5,l6,l7, base + 18432 + 64);
                #pragma unroll
                for (int mb = 0; mb < 2; mb++) {
                    float* D = S[mb][nbl];
                    D[0]=D[1]=D[2]=D[3]=0.f;
                    MMAH(D, qf[mb][0][0],qf[mb][0][1],qf[mb][0][2],qf[mb][0][3], k0,k1);
                    MMAH(D, qf[mb][1][0],qf[mb][1][1],qf[mb][1][2],qf[mb][1][3], k2,k3);
                    MMAH(D, qf[mb][2][0],qf[mb][2][1],qf[mb][2][2],qf[mb][2][3], k4,k5);
                    MMAH(D, qf[mb][3][0],qf[mb][3][1],qf[mb][3][2],qf[mb][3][3], k6,k7);
                    MMAH(D, qf[mb][0][0],qf[mb][0][1],qf[mb][0][2],qf[mb][0][3], l0,l1);
                    MMAH(D, qf[mb][1][0],qf[mb][1][1],qf[mb][1][2],qf[mb][1][3], l2,l3);
                    MMAH(D, qf[mb][2][0],qf[mb][2][1],qf[mb][2][2],qf[mb][2][3], l4,l5);
                    MMAH(D, qf[mb][3][0],qf[mb][3][1],qf[mb][3][2],qf[mb][3][3], l6,l7);
                }
            }

            // exp2 (MUFU) + row-sum partials + pack P (bf16)
            #pragma unroll
            for (int mb = 0; mb < 2; mb++) {
                #pragma unroll
                for (int ksl = 0; ksl < 2; ksl++) {
                    const float* SA = S[mb][2*ksl];
                    const float* SB = S[mb][2*ksl+1];
                    float eA0 = ex2f(SA[0]), eA1 = ex2f(SA[1]);
                    float eA2 = ex2f(SA[2]), eA3 = ex2f(SA[3]);
                    float eB0 = ex2f(SB[0]), eB1 = ex2f(SB[1]);
                    float eB2 = ex2f(SB[2]), eB3 = ex2f(SB[3]);
                    srow[mb][0] += (eA0 + eA1) + (eB0 + eB1);
                    srow[mb][1] += (eA2 + eA3) + (eB2 + eB3);
                    ahh2[ph][mb][ksl][0] = pkbf2(eA0, eA1);
                    ahh2[ph][mb][ksl][1] = pkbf2(eA2, eA3);
                    ahh2[ph][mb][ksl][2] = pkbf2(eB0, eB1);
                    ahh2[ph][mb][ksl][3] = pkbf2(eB2, eB3);
                }
            }
        }

        // ---- Deferred GEMM2 for both halves ----
        #pragma unroll
        for (int ph = 0; ph < 2; ph++) {
            const int h = ph ^ jh;
            #pragma unroll
            for (int nbO = 0; nbO < 8; nbO++) {
                u32 base = sb + SV_H + (u32)((nbO*8 + (lane&7))*272 + jcol0*2 + ((lane>>3)*16)) + h*64;
                u32 v0,v1,v2,v3;
                LDSM4(v0,v1,v2,v3, base);
                #pragma unroll
                for (int mb = 0; mb < 2; mb++) {
                    float* D = O[mb][nbO];
                    MMAB(D, ahh2[ph][mb][0][0],ahh2[ph][mb][0][1],ahh2[ph][mb][0][2],ahh2[ph][mb][0][3], v0,v1);
                    MMAB(D, ahh2[ph][mb][1][0],ahh2[ph][mb][1][1],ahh2[ph][mb][1][2],ahh2[ph][mb][1][3], v2,v3);
                }
            }
        }
    }

    // ---- epilogue: combine j-halves ----
    #pragma unroll
    for (int mb = 0; mb < 2; mb++)
        #pragma unroll
        for (int rr = 0; rr < 2; rr++) {
            float v = srow[mb][rr];
            v += __shfl_xor_sync(0xffffffffu, v, 1);
            v += __shfl_xor_sync(0xffffffffu, v, 2);
            srow[mb][rr] = v;
        }

    float* Stg = (float*)sm2;                 // [128 threads][68] padded
    float* Ls  = (float*)(sm2 + 36864);       // [128 rows][2]
    if ((lane & 3) == 0) {
        #pragma unroll
        for (int mb = 0; mb < 2; mb++) {
            int row = i0 + mb*16 + (lane>>2);
            Ls[row*2 + jh]     = srow[mb][0];
            Ls[(row+8)*2 + jh] = srow[mb][1];
        }
    }
    if (jh == 1) {
        float* dst = Stg + (rg*32 + lane)*68;
        #pragma unroll
        for (int mb = 0; mb < 2; mb++)
            #pragma unroll
            for (int nb = 0; nb < 8; nb++)
                *(float4*)&dst[(mb*8+nb)*4] = *(float4*)O[mb][nb];
    }
    __syncthreads();

    if (jh == 0) {
        const float g = gamma[0];
        const float* src = Stg + (rg*32 + lane)*68;
        float rs[2][2];
        #pragma unroll
        for (int mb = 0; mb < 2; mb++) {
            int row = i0 + mb*16 + (lane>>2);
            rs[mb][0] = 1.0f / (Ls[row*2]     + Ls[row*2 + 1]);
            rs[mb][1] = 1.0f / (Ls[(row+8)*2] + Ls[(row+8)*2 + 1]);
        }
        #pragma unroll
        for (int mb = 0; mb < 2; mb++) {
            #pragma unroll
            for (int nb = 0; nb < 8; nb++) {
                float4 p = *(const float4*)&src[(mb*8+nb)*4];
                float o0 = O[mb][nb][0] + p.x;
                float o1 = O[mb][nb][1] + p.y;
                float o2 = O[mb][nb][2] + p.z;
                float o3 = O[mb][nb][3] + p.w;
                int irow = ibase + i0 + mb*16 + (lane>>2);
                int c = nb*8 + (lane&3)*2;
                size_t off = (size_t)b*CC*NN + (size_t)c*NN + irow;
                out[off]      = g*(o0*rs[mb][0]) + x[off];
                out[off+NN]   = g*(o1*rs[mb][0]) + x[off+NN];
                out[off+8]    = g*(o2*rs[mb][1]) + x[off+8];
                out[off+NN+8] = g*(o3*rs[mb][1]) + x[off+NN+8];
            }
        }
    }
}

// ---------------------------------------------------------------------------
extern "C" void kernel_launch(void* const* d_in, const int* in_sizes, int n_in,
                              void* d_out, int out_size)
{
    const float* x     = (const float*)d_in[0];
    const float* Wq    = (const float*)d_in[1];
    const float* bq    = (const float*)d_in[2];
    const float* Wk    = (const float*)d_in[3];
    const float* bk    = (const float*)d_in[4];
    const float* Wv    = (const float*)d_in[5];
    const float* bv    = (const float*)d_in[6];
    const float* gamma = (const float*)d_in[7];
    float* out = (float*)d_out;

    const int smem1 = (4096 + 3*64*68) * sizeof(float);  // 68,608 B -> 2 CTAs/SM
    const int smem2 = SMEM2;                             // 108,544 B

    cudaFuncSetAttribute(qkv_kernel,  cudaFuncAttributeMaxDynamicSharedMemorySize, smem1);
    cudaFuncSetAttribute(attn_kernel, cudaFuncAttributeMaxDynamicSharedMemorySize, smem2);

    qkv_kernel<<<dim3(64, 4), 256, smem1>>>(x, Wq, bq, Wk, bk, Wv, bv);
    attn_kernel<<<dim3(32, 4), 256, smem2>>>(x, gamma, out);
}